// round 3
// baseline (speedup 1.0000x reference)
#include <cuda_runtime.h>
#include <cstdint>

#define B_      16
#define NCLS_   3
#define CREG_   50
#define H_      96
#define W_      320
#define HW_     (H_*W_)          // 30720
#define TOT_    (B_*NCLS_*HW_)   // 1474560
#define K_      100
#define CAP_    24576
#define SURV_   4096
#define NOUT_   13
#define THRESH_ 0.2f
#define EPS_    1e-6f
// sigmoid(x) >= 0.2  <=>  x >= -ln(4) = -1.3862944; conservative prefilter
#define RAW_PRE (-1.39f)
// raw-space reject margin: for raw<8, sigmoid gap over 0.01 raw >= ~50 ulps
#define MARGIN_ (0.01f)

static __device__ unsigned long long g_cand[B_][CAP_];
static __device__ int                g_cnt[B_];
static __device__ unsigned long long g_sel[B_*K_];
static __device__ int                g_selcnt[B_];

__device__ __forceinline__ float sigf(float x) { return 1.0f / (1.0f + expf(-x)); }

// ---------------- init ----------------
__global__ void k_init() {
    int i = threadIdx.x;
    if (i < B_) g_cnt[i] = 0;
}

// ---------------- fused NMS on raw logits (sigmoid only for peaks/ties) ----------------
__global__ void k_nms(const float* __restrict__ hmp) {
    int idx = blockIdx.x * blockDim.x + threadIdx.x;
    if (idx >= TOT_) return;
    float raw = __ldg(&hmp[idx]);
    if (raw < RAW_PRE) return;               // any s>=0.2 cell survives this

    int r   = idx % (NCLS_*HW_);
    int b   = idx / (NCLS_*HW_);
    int c   = r / HW_;
    int ind = r % HW_;
    int y   = ind / W_;
    int x   = ind % W_;

    // max of 8 neighbors in raw-logit space (monotone image of sigmoid space)
    const float NEG = -3.0e38f;
    float nmax = NEG;
    bool up = (y > 0), dn = (y < H_-1), lf = (x > 0), rt = (x < W_-1);
    if (up)        nmax = fmaxf(nmax, __ldg(&hmp[idx - W_    ]));
    if (up && lf)  nmax = fmaxf(nmax, __ldg(&hmp[idx - W_ - 1]));
    if (up && rt)  nmax = fmaxf(nmax, __ldg(&hmp[idx - W_ + 1]));
    if (lf)        nmax = fmaxf(nmax, __ldg(&hmp[idx     - 1]));
    if (rt)        nmax = fmaxf(nmax, __ldg(&hmp[idx     + 1]));
    if (dn)        nmax = fmaxf(nmax, __ldg(&hmp[idx + W_    ]));
    if (dn && lf)  nmax = fmaxf(nmax, __ldg(&hmp[idx + W_ - 1]));
    if (dn && rt)  nmax = fmaxf(nmax, __ldg(&hmp[idx + W_ + 1]));

    if (raw < nmax) {
        // definitely rejected unless sigmoid-space float tie
        if (nmax - raw >= MARGIN_ && raw < 8.0f) return;
        // exact check in the reference's sigmoid space
        if (sigf(nmax) > sigf(raw)) return;
    }
    float s = sigf(raw);                     // exact reference formula
    if (!(s >= THRESH_)) return;

    unsigned lo = 0xFFFFFFFFu - (unsigned)(c * HW_ + ind);   // smaller (class,ind) -> larger lo
    unsigned long long key = ((unsigned long long)__float_as_uint(s) << 32) | lo;
    int pos = atomicAdd(&g_cnt[b], 1);
    if (pos < CAP_) g_cand[b][pos] = key;
}

// ---------------- per-batch top-100 (histogram narrow + bitonic) ----------------
__global__ void k_select(void) {
    const int b   = blockIdx.x;
    const int tid = threadIdx.x;            // 256 threads
    __shared__ int hist[320];
    __shared__ int subhist[256];
    __shared__ unsigned long long surv[SURV_];
    __shared__ int s_bstar, s_b2, s_scount, s_target;

    int n = g_cnt[b]; if (n > CAP_) n = CAP_;
    for (int i = tid; i < 320; i += 256) hist[i] = 0;
    for (int i = tid; i < 256; i += 256) subhist[i] = 0;
    __syncthreads();

    for (int i = tid; i < n; i += 256) {
        int bin = (int)(unsigned)(g_cand[b][i] >> 48) - 0x3E4C;
        bin = max(0, min(319, bin));
        atomicAdd(&hist[bin], 1);
    }
    __syncthreads();
    if (tid == 0) {
        int target = n < K_ ? n : K_;
        s_target = target;
        int acc = 0, bst = 0;
        for (int i = 319; i >= 0; --i) { acc += hist[i]; if (acc >= target) { bst = i; break; } }
        s_bstar = bst;
    }
    __syncthreads();
    const int bstar = s_bstar;

    for (int i = tid; i < n; i += 256) {
        unsigned long long key = g_cand[b][i];
        int bin = (int)(unsigned)(key >> 48) - 0x3E4C;
        bin = max(0, min(319, bin));
        if (bin == bstar) atomicAdd(&subhist[(unsigned)(key >> 40) & 0xFF], 1);
    }
    __syncthreads();
    if (tid == 0) {
        int cntabove = 0;
        for (int i = 319; i > bstar; --i) cntabove += hist[i];
        int m = s_target - cntabove; if (m < 1) m = 1;
        int acc = 0, b2 = 0;
        for (int s = 255; s >= 0; --s) { acc += subhist[s]; if (acc >= m) { b2 = s; break; } }
        s_b2 = b2;
        s_scount = 0;
    }
    __syncthreads();
    const int b2 = s_b2;

    for (int i = tid; i < n; i += 256) {
        unsigned long long key = g_cand[b][i];
        int bin = (int)(unsigned)(key >> 48) - 0x3E4C;
        bin = max(0, min(319, bin));
        bool take = (bin > bstar) || (bin == bstar && (int)((key >> 40) & 0xFF) >= b2);
        if (take) {
            int p = atomicAdd(&s_scount, 1);
            if (p < SURV_) surv[p] = key;
        }
    }
    __syncthreads();
    int sc = min(s_scount, SURV_);
    int P = 128; while (P < sc) P <<= 1;
    for (int i = tid; i < P; i += 256) if (i >= sc) surv[i] = 0ULL;
    __syncthreads();

    for (int k = 2; k <= P; k <<= 1) {
        for (int j = k >> 1; j > 0; j >>= 1) {
            for (int i = tid; i < P; i += 256) {
                int ixj = i ^ j;
                if (ixj > i) {
                    bool dir = ((i & k) == 0);
                    unsigned long long a = surv[i], cbb = surv[ixj];
                    if ((a < cbb) == dir) { surv[i] = cbb; surv[ixj] = a; }
                }
            }
            __syncthreads();
        }
    }

    int target = s_target;
    for (int kk = tid; kk < K_; kk += 256)
        if (kk < target) g_sel[b*K_ + kk] = surv[kk];
    if (tid == 0) g_selcnt[b] = target;
}

// ---------------- final math: one warp per detection, lanes parallelize the gather ----------------
__constant__ int c_chan[24] = {0,1,2,3,4,5,6,7,8,
                               26,28,30,32,34,36,38,40,42,44,
                               45,46,47,48,49};

__global__ void k_final(const float* __restrict__ pred_reg,
                        const float* __restrict__ calib,
                        const float* __restrict__ pad_size,
                        const float* __restrict__ dim_mean,
                        float* __restrict__ out) {
    int det  = blockIdx.x;          // 0 .. B*K-1
    int b    = det / K_;
    int k    = det % K_;
    int lane = threadIdx.x;
    float* row = out + (size_t)det * NOUT_;

    if (k >= g_selcnt[b]) {
        if (lane < NOUT_) row[lane] = 0.0f;
        return;
    }
    unsigned long long key = g_sel[det];
    unsigned lo  = 0xFFFFFFFFu - (unsigned)(key & 0xFFFFFFFFu);
    int cls = (int)(lo / HW_);
    int ind = (int)(lo % HW_);

    __shared__ float v[24];
    const float* rb = pred_reg + (size_t)b * CREG_ * HW_ + ind;
    if (lane < 24) v[lane] = __ldg(&rb[c_chan[lane] * HW_]);
    __syncwarp();
    if (lane != 0) return;

    float score = __uint_as_float((unsigned)(key >> 32));
    float fx = (float)(ind % W_);
    float fy = (float)(ind / W_);

    float fu = calib[b*4+0], cu = calib[b*4+1], fv = calib[b*4+2], cv = calib[b*4+3];
    float pw = pad_size[b*2+0], ph = pad_size[b*2+1];

    float r0 = fmaxf(v[0], 0.f), r1 = fmaxf(v[1], 0.f);
    float r2 = fmaxf(v[2], 0.f), r3 = fmaxf(v[3], 0.f);
    const float HIX = (float)(W_*4 - 1), HIY = (float)(H_*4 - 1);
    float bx0 = fminf(fmaxf((fx - r0)*4.f - pw, 0.f), HIX);
    float by0 = fminf(fmaxf((fy - r1)*4.f - ph, 0.f), HIY);
    float bx1 = fminf(fmaxf((fx + r2)*4.f - pw, 0.f), HIX);
    float by1 = fminf(fmaxf((fy + r3)*4.f - ph, 0.f), HIY);

    const float* dm = dim_mean + cls*3;
    float d0 = expf(v[6]) * dm[0];
    float d1 = expf(v[7]) * dm[1];
    float d2 = expf(v[8]) * dm[2];
    float h3d = d1;

    // v[9..18] = kpt y's (channels 26,28,...,44)
    float fh = fu * h3d;
    float d_ctr = fh / (fmaxf(v[17] - v[18], 0.f)*4.f + EPS_);
    float d_02  = 0.5f * (fh / (fmaxf(v[9]  - v[13], 0.f)*4.f + EPS_)
                        + fh / (fmaxf(v[11] - v[15], 0.f)*4.f + EPS_));
    float d_13  = 0.5f * (fh / (fmaxf(v[10] - v[14], 0.f)*4.f + EPS_)
                        + fh / (fmaxf(v[12] - v[16], 0.f)*4.f + EPS_));
    float kd0 = fminf(fmaxf(d_ctr, 0.1f), 100.f);
    float kd1 = fminf(fmaxf(d_02 , 0.1f), 100.f);
    float kd2 = fminf(fmaxf(d_13 , 0.1f), 100.f);

    float doff   = v[22];
    float sgd    = 1.0f / (1.0f + expf(-doff));
    float direct = fminf(fmaxf(1.0f / sgd - 1.0f, 0.1f), 100.f);

    float u0 = expf(v[23]);   // dunc (ch 49)
    float u1 = expf(v[19]);   // cunc (ch 45)
    float u2 = expf(v[20]);
    float u3 = expf(v[21]);
    float w0 = 1.f/u0, w1 = 1.f/u1, w2 = 1.f/u2, w3 = 1.f/u3;
    float S  = w0 + w1 + w2 + w3;
    w0 /= S; w1 /= S; w2 /= S; w3 /= S;
    float depth = direct*w0 + kd0*w1 + kd1*w2 + kd2*w3;
    float derr  = w0*u0 + w1*u1 + w2*u2 + w3*u3;

    float projx = (fx + v[4])*4.f - pw;
    float projy = (fy + v[5])*4.f - ph;
    float x3 = (projx - cu) * depth / fu;
    float y3 = (projy - cv) * depth / fv;

    row[0]  = (float)cls;
    row[1]  = score;
    row[2]  = bx0;  row[3]  = by0;  row[4]  = bx1;  row[5]  = by1;
    row[6]  = d0;   row[7]  = d1;   row[8]  = d2;
    row[9]  = x3;   row[10] = y3;   row[11] = depth;
    row[12] = derr;
}

extern "C" void kernel_launch(void* const* d_in, const int* in_sizes, int n_in,
                              void* d_out, int out_size) {
    const float* pred_hmp = (const float*)d_in[0];
    const float* pred_reg = (const float*)d_in[1];
    const float* calib    = (const float*)d_in[2];
    const float* pad_size = (const float*)d_in[3];
    const float* dim_mean = (const float*)d_in[4];
    float* out = (float*)d_out;

    k_init<<<1, 32>>>();
    k_nms<<<(TOT_ + 255)/256, 256>>>(pred_hmp);
    k_select<<<B_, 256>>>();
    k_final<<<B_*K_, 32>>>(pred_reg, calib, pad_size, dim_mean, out);
}

// round 4
// speedup vs baseline: 3.6991x; 3.6991x over previous
#include <cuda_runtime.h>
#include <cstdint>

#define B_      16
#define NCLS_   3
#define CREG_   50
#define H_      96
#define W_      320
#define HW_     (H_*W_)          // 30720
#define TOT_    (B_*NCLS_*HW_)   // 1474560
#define K_      100
#define CAP_    24576
#define SURV_   4096
#define NOUT_   13
#define THRESH_ 0.2f
#define EPS_    1e-6f
#define RAW_PRE (-1.39f)         // sigmoid(x)>=0.2 <=> x>=-1.3862944; conservative
#define MARGIN_ (0.01f)          // raw-gap below which we double-check in sigmoid space
#define TILE_Y  8
#define NTB     (H_/TILE_Y)      // 12 stripes
#define LBUF_   2048

static __device__ unsigned long long g_cand[B_][CAP_];
static __device__ int                g_cnt[B_];
static __device__ unsigned long long g_sel[B_*K_];
static __device__ int                g_selcnt[B_];

__device__ __forceinline__ float sigf(float x) { return 1.0f / (1.0f + expf(-x)); }

// ---------------- init ----------------
__global__ void k_init() {
    int i = threadIdx.x;
    if (i < B_) g_cnt[i] = 0;
}

// ---------------- tiled NMS: coalesced loads + smem 3x3 max ----------------
__global__ void __launch_bounds__(W_) k_nms(const float* __restrict__ hmp) {
    __shared__ float tile[TILE_Y+2][W_];
    __shared__ unsigned long long lbuf[LBUF_];
    __shared__ int lcnt, gbase;

    int blk = blockIdx.x;
    int bc  = blk / NTB;             // b*NCLS + c
    int t   = blk % NTB;
    int b   = bc / NCLS_;
    int c   = bc % NCLS_;
    int y0  = t * TILE_Y;
    int x   = threadIdx.x;           // 0..319

    const float* base = hmp + (size_t)bc * HW_;
    #pragma unroll
    for (int r = 0; r < TILE_Y+2; ++r) {
        int gy = y0 + r - 1;
        tile[r][x] = (gy >= 0 && gy < H_) ? __ldg(&base[gy*W_ + x]) : -3.0e38f;
    }
    if (x == 0) lcnt = 0;
    __syncthreads();

    bool lf = (x > 0), rt = (x < W_-1);
    #pragma unroll
    for (int ly = 0; ly < TILE_Y; ++ly) {
        float raw = tile[ly+1][x];
        if (raw < RAW_PRE) continue;
        float m = fmaxf(tile[ly][x], tile[ly+2][x]);
        if (lf) m = fmaxf(m, fmaxf(tile[ly][x-1], fmaxf(tile[ly+1][x-1], tile[ly+2][x-1])));
        if (rt) m = fmaxf(m, fmaxf(tile[ly][x+1], fmaxf(tile[ly+1][x+1], tile[ly+2][x+1])));
        if (raw < m) {
            if (m - raw >= MARGIN_ && raw < 8.0f) continue;   // safe raw-space reject
            if (sigf(m) > sigf(raw)) continue;                // exact tie resolution
        }
        float s = sigf(raw);                                  // exact reference sigmoid
        if (!(s >= THRESH_)) continue;
        int ind = (y0 + ly)*W_ + x;
        unsigned lo = 0xFFFFFFFFu - (unsigned)(c*HW_ + ind);
        unsigned long long key = ((unsigned long long)__float_as_uint(s) << 32) | lo;
        int p = atomicAdd(&lcnt, 1);
        if (p < LBUF_) lbuf[p] = key;
        else {  // overflow fallback (order-independent: keys fully determine sort)
            int gp = atomicAdd(&g_cnt[b], 1);
            if (gp < CAP_) g_cand[b][gp] = key;
        }
    }
    __syncthreads();
    int n = min(lcnt, LBUF_);
    if (x == 0) gbase = atomicAdd(&g_cnt[b], n);
    __syncthreads();
    int gb = gbase;
    for (int i = x; i < n; i += W_) {
        int gp = gb + i;
        if (gp < CAP_) g_cand[b][gp] = lbuf[i];
    }
}

// ---------------- per-batch top-100 (histogram narrow + bitonic) ----------------
__global__ void k_select(void) {
    const int b   = blockIdx.x;
    const int tid = threadIdx.x;            // 256 threads
    __shared__ int hist[320];
    __shared__ int subhist[256];
    __shared__ unsigned long long surv[SURV_];
    __shared__ int s_bstar, s_b2, s_scount, s_target;

    int n = g_cnt[b]; if (n > CAP_) n = CAP_;
    for (int i = tid; i < 320; i += 256) hist[i] = 0;
    for (int i = tid; i < 256; i += 256) subhist[i] = 0;
    __syncthreads();

    for (int i = tid; i < n; i += 256) {
        int bin = (int)(unsigned)(g_cand[b][i] >> 48) - 0x3E4C;
        bin = max(0, min(319, bin));
        atomicAdd(&hist[bin], 1);
    }
    __syncthreads();
    if (tid == 0) {
        int target = n < K_ ? n : K_;
        s_target = target;
        int acc = 0, bst = 0;
        for (int i = 319; i >= 0; --i) { acc += hist[i]; if (acc >= target) { bst = i; break; } }
        s_bstar = bst;
    }
    __syncthreads();
    const int bstar = s_bstar;

    for (int i = tid; i < n; i += 256) {
        unsigned long long key = g_cand[b][i];
        int bin = (int)(unsigned)(key >> 48) - 0x3E4C;
        bin = max(0, min(319, bin));
        if (bin == bstar) atomicAdd(&subhist[(unsigned)(key >> 40) & 0xFF], 1);
    }
    __syncthreads();
    if (tid == 0) {
        int cntabove = 0;
        for (int i = 319; i > bstar; --i) cntabove += hist[i];
        int m = s_target - cntabove; if (m < 1) m = 1;
        int acc = 0, b2 = 0;
        for (int s = 255; s >= 0; --s) { acc += subhist[s]; if (acc >= m) { b2 = s; break; } }
        s_b2 = b2;
        s_scount = 0;
    }
    __syncthreads();
    const int b2 = s_b2;

    for (int i = tid; i < n; i += 256) {
        unsigned long long key = g_cand[b][i];
        int bin = (int)(unsigned)(key >> 48) - 0x3E4C;
        bin = max(0, min(319, bin));
        bool take = (bin > bstar) || (bin == bstar && (int)((key >> 40) & 0xFF) >= b2);
        if (take) {
            int p = atomicAdd(&s_scount, 1);
            if (p < SURV_) surv[p] = key;
        }
    }
    __syncthreads();
    int sc = min(s_scount, SURV_);
    int P = 128; while (P < sc) P <<= 1;
    for (int i = tid; i < P; i += 256) if (i >= sc) surv[i] = 0ULL;
    __syncthreads();

    for (int k = 2; k <= P; k <<= 1) {
        for (int j = k >> 1; j > 0; j >>= 1) {
            for (int i = tid; i < P; i += 256) {
                int ixj = i ^ j;
                if (ixj > i) {
                    bool dir = ((i & k) == 0);
                    unsigned long long a = surv[i], cbb = surv[ixj];
                    if ((a < cbb) == dir) { surv[i] = cbb; surv[ixj] = a; }
                }
            }
            __syncthreads();
        }
    }

    int target = s_target;
    for (int kk = tid; kk < K_; kk += 256)
        if (kk < target) g_sel[b*K_ + kk] = surv[kk];
    if (tid == 0) g_selcnt[b] = target;
}

// ---------------- final math: warp per detection, 4 warps/block ----------------
__constant__ int c_chan[24] = {0,1,2,3,4,5,6,7,8,
                               26,28,30,32,34,36,38,40,42,44,
                               45,46,47,48,49};

__global__ void k_final(const float* __restrict__ pred_reg,
                        const float* __restrict__ calib,
                        const float* __restrict__ pad_size,
                        const float* __restrict__ dim_mean,
                        float* __restrict__ out) {
    int w    = threadIdx.x >> 5;
    int lane = threadIdx.x & 31;
    int det  = blockIdx.x * 4 + w;          // 0 .. B*K-1
    if (det >= B_*K_) return;
    int b    = det / K_;
    int k    = det % K_;
    float* row = out + (size_t)det * NOUT_;

    if (k >= g_selcnt[b]) {
        if (lane < NOUT_) row[lane] = 0.0f;
        return;
    }
    unsigned long long key = g_sel[det];
    unsigned lo  = 0xFFFFFFFFu - (unsigned)(key & 0xFFFFFFFFu);
    int cls = (int)(lo / HW_);
    int ind = (int)(lo % HW_);

    __shared__ float vs[4][24];
    float* v = vs[w];
    const float* rb = pred_reg + (size_t)b * CREG_ * HW_ + ind;
    if (lane < 24) v[lane] = __ldg(&rb[c_chan[lane] * HW_]);
    __syncwarp();
    if (lane != 0) return;

    float score = __uint_as_float((unsigned)(key >> 32));
    float fx = (float)(ind % W_);
    float fy = (float)(ind / W_);

    float fu = calib[b*4+0], cu = calib[b*4+1], fv = calib[b*4+2], cv = calib[b*4+3];
    float pw = pad_size[b*2+0], ph = pad_size[b*2+1];

    float r0 = fmaxf(v[0], 0.f), r1 = fmaxf(v[1], 0.f);
    float r2 = fmaxf(v[2], 0.f), r3 = fmaxf(v[3], 0.f);
    const float HIX = (float)(W_*4 - 1), HIY = (float)(H_*4 - 1);
    float bx0 = fminf(fmaxf((fx - r0)*4.f - pw, 0.f), HIX);
    float by0 = fminf(fmaxf((fy - r1)*4.f - ph, 0.f), HIY);
    float bx1 = fminf(fmaxf((fx + r2)*4.f - pw, 0.f), HIX);
    float by1 = fminf(fmaxf((fy + r3)*4.f - ph, 0.f), HIY);

    const float* dm = dim_mean + cls*3;
    float d0 = expf(v[6]) * dm[0];
    float d1 = expf(v[7]) * dm[1];
    float d2 = expf(v[8]) * dm[2];
    float h3d = d1;

    // v[9..18] = kpt y's (channels 26,28,...,44)
    float fh = fu * h3d;
    float d_ctr = fh / (fmaxf(v[17] - v[18], 0.f)*4.f + EPS_);
    float d_02  = 0.5f * (fh / (fmaxf(v[9]  - v[13], 0.f)*4.f + EPS_)
                        + fh / (fmaxf(v[11] - v[15], 0.f)*4.f + EPS_));
    float d_13  = 0.5f * (fh / (fmaxf(v[10] - v[14], 0.f)*4.f + EPS_)
                        + fh / (fmaxf(v[12] - v[16], 0.f)*4.f + EPS_));
    float kd0 = fminf(fmaxf(d_ctr, 0.1f), 100.f);
    float kd1 = fminf(fmaxf(d_02 , 0.1f), 100.f);
    float kd2 = fminf(fmaxf(d_13 , 0.1f), 100.f);

    float doff   = v[22];
    float sgd    = 1.0f / (1.0f + expf(-doff));
    float direct = fminf(fmaxf(1.0f / sgd - 1.0f, 0.1f), 100.f);

    float u0 = expf(v[23]);   // dunc (ch 49)
    float u1 = expf(v[19]);   // cunc (ch 45..47)
    float u2 = expf(v[20]);
    float u3 = expf(v[21]);
    float w0 = 1.f/u0, w1 = 1.f/u1, w2 = 1.f/u2, w3 = 1.f/u3;
    float S  = w0 + w1 + w2 + w3;
    w0 /= S; w1 /= S; w2 /= S; w3 /= S;
    float depth = direct*w0 + kd0*w1 + kd1*w2 + kd2*w3;
    float derr  = w0*u0 + w1*u1 + w2*u2 + w3*u3;

    float projx = (fx + v[4])*4.f - pw;
    float projy = (fy + v[5])*4.f - ph;
    float x3 = (projx - cu) * depth / fu;
    float y3 = (projy - cv) * depth / fv;

    row[0]  = (float)cls;
    row[1]  = score;
    row[2]  = bx0;  row[3]  = by0;  row[4]  = bx1;  row[5]  = by1;
    row[6]  = d0;   row[7]  = d1;   row[8]  = d2;
    row[9]  = x3;   row[10] = y3;   row[11] = depth;
    row[12] = derr;
}

extern "C" void kernel_launch(void* const* d_in, const int* in_sizes, int n_in,
                              void* d_out, int out_size) {
    const float* pred_hmp = (const float*)d_in[0];
    const float* pred_reg = (const float*)d_in[1];
    const float* calib    = (const float*)d_in[2];
    const float* pad_size = (const float*)d_in[3];
    const float* dim_mean = (const float*)d_in[4];
    float* out = (float*)d_out;

    k_init<<<1, 32>>>();
    k_nms<<<B_*NCLS_*NTB, W_>>>(pred_hmp);
    k_select<<<B_, 256>>>();
    k_final<<<(B_*K_ + 3)/4, 128>>>(pred_reg, calib, pad_size, dim_mean, out);
}

// round 5
// speedup vs baseline: 4.4073x; 1.1914x over previous
#include <cuda_runtime.h>
#include <cstdint>

#define B_      16
#define NCLS_   3
#define CREG_   50
#define H_      96
#define W_      320
#define HW_     (H_*W_)          // 30720
#define K_      100
#define CAP_    24576
#define CCAP_   8192
#define SURV_   4096
#define NOUT_   13
#define THRESH_ 0.2f
#define EPS_    1e-6f
#define RAW_PRE (-1.39f)         // sigmoid(x)>=0.2 <=> x>=-1.3862944; conservative
#define MARGIN_ (0.01f)          // raw-gap below which we double-check in sigmoid space
#define TILE_Y  16
#define NTB     (H_/TILE_Y)      // 6 stripes
#define LBUF_   1024
#define NT_     512

static __device__ unsigned long long g_cand[B_][CAP_];
static __device__ int                g_cnt[B_];   // static zero-init; re-zeroed by k_selfin

__device__ __forceinline__ float sigf(float x) { return 1.0f / (1.0f + expf(-x)); }

// ---------------- tiled NMS: coalesced loads + smem 3x3 max ----------------
__global__ void __launch_bounds__(W_) k_nms(const float* __restrict__ hmp) {
    __shared__ float tile[TILE_Y+2][W_];
    __shared__ unsigned long long lbuf[LBUF_];
    __shared__ int lcnt, gbase;

    int blk = blockIdx.x;
    int bc  = blk / NTB;             // b*NCLS + c
    int t   = blk % NTB;
    int b   = bc / NCLS_;
    int c   = bc % NCLS_;
    int y0  = t * TILE_Y;
    int x   = threadIdx.x;           // 0..319

    const float* base = hmp + (size_t)bc * HW_;
    #pragma unroll
    for (int r = 0; r < TILE_Y+2; ++r) {
        int gy = y0 + r - 1;
        tile[r][x] = (gy >= 0 && gy < H_) ? __ldg(&base[gy*W_ + x]) : -3.0e38f;
    }
    if (x == 0) lcnt = 0;
    __syncthreads();

    bool lf = (x > 0), rt = (x < W_-1);
    #pragma unroll
    for (int ly = 0; ly < TILE_Y; ++ly) {
        float raw = tile[ly+1][x];
        if (raw < RAW_PRE) continue;
        float m = fmaxf(tile[ly][x], tile[ly+2][x]);
        if (lf) m = fmaxf(m, fmaxf(tile[ly][x-1], fmaxf(tile[ly+1][x-1], tile[ly+2][x-1])));
        if (rt) m = fmaxf(m, fmaxf(tile[ly][x+1], fmaxf(tile[ly+1][x+1], tile[ly+2][x+1])));
        if (raw < m) {
            if (m - raw >= MARGIN_ && raw < 8.0f) continue;   // safe raw-space reject
            if (sigf(m) > sigf(raw)) continue;                // exact sigmoid-space tie check
        }
        float s = sigf(raw);                                  // exact reference sigmoid
        if (!(s >= THRESH_)) continue;
        int ind = (y0 + ly)*W_ + x;
        unsigned lo = 0xFFFFFFFFu - (unsigned)(c*HW_ + ind);
        unsigned long long key = ((unsigned long long)__float_as_uint(s) << 32) | lo;
        int p = atomicAdd(&lcnt, 1);
        if (p < LBUF_) lbuf[p] = key;
        else {  // overflow fallback (order-independent: keys fully determine sort)
            int gp = atomicAdd(&g_cnt[b], 1);
            if (gp < CAP_) g_cand[b][gp] = key;
        }
    }
    __syncthreads();
    int n = min(lcnt, LBUF_);
    if (x == 0) gbase = atomicAdd(&g_cnt[b], n);
    __syncthreads();
    int gb = gbase;
    for (int i = x; i < n; i += W_) {
        int gp = gb + i;
        if (gp < CAP_) g_cand[b][gp] = lbuf[i];
    }
}

// ---------------- fused top-100 select + final math, one block per batch ----------------
__constant__ int c_chan[24] = {0,1,2,3,4,5,6,7,8,
                               26,28,30,32,34,36,38,40,42,44,
                               45,46,47,48,49};

__global__ void __launch_bounds__(NT_) k_selfin(
        const float* __restrict__ pred_reg,
        const float* __restrict__ calib,
        const float* __restrict__ pad_size,
        const float* __restrict__ dim_mean,
        float* __restrict__ out) {
    const int b   = blockIdx.x;
    const int tid = threadIdx.x;            // 0..511
    __shared__ int S[512];                  // padded 320-bin suffix sums
    __shared__ int SS[256];                 // 256-bin suffix sums
    __shared__ unsigned long long cache[CCAP_];
    __shared__ unsigned long long surv[SURV_];
    __shared__ float gv[K_][24];
    __shared__ int s_bstar, s_b2, s_scount;

    int n = g_cnt[b]; if (n > CAP_) n = CAP_;
    int target = n < K_ ? n : K_;

    if (n > 0) {
        // pass 1: coarse histogram on scoreBits>>16, cache candidates in smem
        S[tid] = 0;
        if (tid < 256) SS[tid] = 0;
        __syncthreads();
        for (int i = tid; i < n; i += NT_) {
            unsigned long long key = g_cand[b][i];
            if (i < CCAP_) cache[i] = key;
            int bin = (int)(unsigned)(key >> 48) - 0x3E4C;
            bin = max(0, min(319, bin));
            atomicAdd(&S[bin], 1);
        }
        __syncthreads();
        // suffix sum over 512 (Hillis-Steele)
        #pragma unroll
        for (int off = 1; off < 512; off <<= 1) {
            int v = (tid + off < 512) ? S[tid + off] : 0;
            __syncthreads();
            S[tid] += v;
            __syncthreads();
        }
        // bstar: largest i with S[i] >= target  (S non-increasing)
        if (tid < 320) {
            int nxt = (tid + 1 < 512) ? S[tid + 1] : 0;
            if (S[tid] >= target && nxt < target) s_bstar = tid;
        }
        __syncthreads();
        const int bstar = s_bstar;
        const int m = max(1, target - S[bstar + 1]);   // needed from bin bstar

        // pass 2: refine within cutoff bin on next 8 bits
        for (int i = tid; i < n; i += NT_) {
            unsigned long long key = (i < CCAP_) ? cache[i] : g_cand[b][i];
            int bin = (int)(unsigned)(key >> 48) - 0x3E4C;
            bin = max(0, min(319, bin));
            if (bin == bstar) atomicAdd(&SS[(unsigned)(key >> 40) & 0xFF], 1);
        }
        __syncthreads();
        #pragma unroll
        for (int off = 1; off < 256; off <<= 1) {
            int v = (tid < 256 && tid + off < 256) ? SS[tid + off] : 0;
            __syncthreads();
            if (tid < 256) SS[tid] += v;
            __syncthreads();
        }
        if (tid < 256) {
            int nxt = (tid + 1 < 256) ? SS[tid + 1] : 0;
            if (SS[tid] >= m && nxt < m) s_b2 = tid;
        }
        if (tid == 0) s_scount = 0;
        __syncthreads();
        const int b2 = s_b2;

        // pass 3: collect survivors
        for (int i = tid; i < n; i += NT_) {
            unsigned long long key = (i < CCAP_) ? cache[i] : g_cand[b][i];
            int bin = (int)(unsigned)(key >> 48) - 0x3E4C;
            bin = max(0, min(319, bin));
            bool take = (bin > bstar) || (bin == bstar && (int)((key >> 40) & 0xFF) >= b2);
            if (take) {
                int p = atomicAdd(&s_scount, 1);
                if (p < SURV_) surv[p] = key;
            }
        }
        __syncthreads();
        int sc = min(s_scount, SURV_);
        int P = 128; while (P < sc) P <<= 1;
        for (int i = tid; i < P; i += NT_) if (i >= sc) surv[i] = 0ULL;
        __syncthreads();

        // bitonic sort descending on full 64-bit keys (exact reference tie order)
        for (int k = 2; k <= P; k <<= 1) {
            for (int j = k >> 1; j > 0; j >>= 1) {
                for (int i = tid; i < P; i += NT_) {
                    int ixj = i ^ j;
                    if (ixj > i) {
                        bool dir = ((i & k) == 0);
                        unsigned long long a = surv[i], cbb = surv[ixj];
                        if ((a < cbb) == dir) { surv[i] = cbb; surv[ixj] = a; }
                    }
                }
                __syncthreads();
            }
        }

        // gather 24 channels per selected detection (latency-parallel)
        const float* rbase = pred_reg + (size_t)b * CREG_ * HW_;
        for (int i = tid; i < target * 24; i += NT_) {
            int d  = i / 24;
            int ch = i % 24;
            unsigned lo = 0xFFFFFFFFu - (unsigned)(surv[d] & 0xFFFFFFFFu);
            int ind = (int)(lo % HW_);
            gv[d][ch] = __ldg(&rbase[c_chan[ch] * HW_ + ind]);
        }
        __syncthreads();
    }

    // reset counter for next graph replay (deterministic: always ends zeroed)
    if (tid == 0) g_cnt[b] = 0;

    if (tid >= K_) return;
    float* row = out + (size_t)(b*K_ + tid) * NOUT_;
    if (tid >= target) {
        #pragma unroll
        for (int j = 0; j < NOUT_; ++j) row[j] = 0.0f;
        return;
    }

    unsigned long long key = surv[tid];
    float score = __uint_as_float((unsigned)(key >> 32));
    unsigned lo = 0xFFFFFFFFu - (unsigned)(key & 0xFFFFFFFFu);
    int cls = (int)(lo / HW_);
    int ind = (int)(lo % HW_);
    float fx = (float)(ind % W_);
    float fy = (float)(ind / W_);
    const float* v = gv[tid];

    float fu = calib[b*4+0], cu = calib[b*4+1], fv = calib[b*4+2], cv = calib[b*4+3];
    float pw = pad_size[b*2+0], ph = pad_size[b*2+1];

    float r0 = fmaxf(v[0], 0.f), r1 = fmaxf(v[1], 0.f);
    float r2 = fmaxf(v[2], 0.f), r3 = fmaxf(v[3], 0.f);
    const float HIX = (float)(W_*4 - 1), HIY = (float)(H_*4 - 1);
    float bx0 = fminf(fmaxf((fx - r0)*4.f - pw, 0.f), HIX);
    float by0 = fminf(fmaxf((fy - r1)*4.f - ph, 0.f), HIY);
    float bx1 = fminf(fmaxf((fx + r2)*4.f - pw, 0.f), HIX);
    float by1 = fminf(fmaxf((fy + r3)*4.f - ph, 0.f), HIY);

    const float* dm = dim_mean + cls*3;
    float d0 = expf(v[6]) * dm[0];
    float d1 = expf(v[7]) * dm[1];
    float d2 = expf(v[8]) * dm[2];
    float h3d = d1;

    // v[9..18] = kpt y's (channels 26,28,...,44)
    float fh = fu * h3d;
    float d_ctr = fh / (fmaxf(v[17] - v[18], 0.f)*4.f + EPS_);
    float d_02  = 0.5f * (fh / (fmaxf(v[9]  - v[13], 0.f)*4.f + EPS_)
                        + fh / (fmaxf(v[11] - v[15], 0.f)*4.f + EPS_));
    float d_13  = 0.5f * (fh / (fmaxf(v[10] - v[14], 0.f)*4.f + EPS_)
                        + fh / (fmaxf(v[12] - v[16], 0.f)*4.f + EPS_));
    float kd0 = fminf(fmaxf(d_ctr, 0.1f), 100.f);
    float kd1 = fminf(fmaxf(d_02 , 0.1f), 100.f);
    float kd2 = fminf(fmaxf(d_13 , 0.1f), 100.f);

    float doff   = v[22];
    float sgd    = 1.0f / (1.0f + expf(-doff));
    float direct = fminf(fmaxf(1.0f / sgd - 1.0f, 0.1f), 100.f);

    float u0 = expf(v[23]);   // dunc (ch 49)
    float u1 = expf(v[19]);   // cunc (ch 45..47)
    float u2 = expf(v[20]);
    float u3 = expf(v[21]);
    float w0 = 1.f/u0, w1 = 1.f/u1, w2 = 1.f/u2, w3 = 1.f/u3;
    float Sw = w0 + w1 + w2 + w3;
    w0 /= Sw; w1 /= Sw; w2 /= Sw; w3 /= Sw;
    float depth = direct*w0 + kd0*w1 + kd1*w2 + kd2*w3;
    float derr  = w0*u0 + w1*u1 + w2*u2 + w3*u3;

    float projx = (fx + v[4])*4.f - pw;
    float projy = (fy + v[5])*4.f - ph;
    float x3 = (projx - cu) * depth / fu;
    float y3 = (projy - cv) * depth / fv;

    row[0]  = (float)cls;
    row[1]  = score;
    row[2]  = bx0;  row[3]  = by0;  row[4]  = bx1;  row[5]  = by1;
    row[6]  = d0;   row[7]  = d1;   row[8]  = d2;
    row[9]  = x3;   row[10] = y3;   row[11] = depth;
    row[12] = derr;
}

extern "C" void kernel_launch(void* const* d_in, const int* in_sizes, int n_in,
                              void* d_out, int out_size) {
    const float* pred_hmp = (const float*)d_in[0];
    const float* pred_reg = (const float*)d_in[1];
    const float* calib    = (const float*)d_in[2];
    const float* pad_size = (const float*)d_in[3];
    const float* dim_mean = (const float*)d_in[4];
    float* out = (float*)d_out;

    k_nms<<<B_*NCLS_*NTB, W_>>>(pred_hmp);
    k_selfin<<<B_, NT_>>>(pred_reg, calib, pad_size, dim_mean, out);
}

// round 8
// speedup vs baseline: 5.1894x; 1.1775x over previous
#include <cuda_runtime.h>
#include <cstdint>

#define B_      16
#define NCLS_   3
#define CREG_   50
#define H_      96
#define W_      320
#define HW_     (H_*W_)          // 30720
#define K_      100
#define CAP_    24576
#define SURV_   2048
#define NOUT_   13
#define THRESH_ 0.2f
#define EPS_    1e-6f
#define RAW_PRE (-1.39f)
#define MARGIN_ (0.01f)
#define TILE_Y  16
#define NTB     (H_/TILE_Y)      // 6 stripes
#define LBUF_   1024
#define NT_     512

static __device__ unsigned long long g_cand[B_][CAP_];
static __device__ int                g_cnt[B_];        // zero-init; re-zeroed by k_selfin
static __device__ int                g_hist[B_][512];  // zero-init; re-zeroed by k_selfin

__device__ __forceinline__ float sigf(float x) { return 1.0f / (1.0f + expf(-x)); }

// ---------------- tiled NMS + candidate append + global histogram ----------------
__global__ void __launch_bounds__(W_) k_nms(const float* __restrict__ hmp) {
    __shared__ float tile[TILE_Y+2][W_];
    __shared__ unsigned long long lbuf[LBUF_];
    __shared__ int lcnt, gbase;

    int blk = blockIdx.x;
    int bc  = blk / NTB;             // b*NCLS + c
    int t   = blk % NTB;
    int b   = bc / NCLS_;
    int c   = bc % NCLS_;
    int y0  = t * TILE_Y;
    int x   = threadIdx.x;           // 0..319

    const float* base = hmp + (size_t)bc * HW_;
    #pragma unroll
    for (int r = 0; r < TILE_Y+2; ++r) {
        int gy = y0 + r - 1;
        tile[r][x] = (gy >= 0 && gy < H_) ? __ldg(&base[gy*W_ + x]) : -3.0e38f;
    }
    if (x == 0) lcnt = 0;
    __syncthreads();

    bool lf = (x > 0), rt = (x < W_-1);
    #pragma unroll
    for (int ly = 0; ly < TILE_Y; ++ly) {
        float raw = tile[ly+1][x];
        if (raw < RAW_PRE) continue;
        float m = fmaxf(tile[ly][x], tile[ly+2][x]);
        if (lf) m = fmaxf(m, fmaxf(tile[ly][x-1], fmaxf(tile[ly+1][x-1], tile[ly+2][x-1])));
        if (rt) m = fmaxf(m, fmaxf(tile[ly][x+1], fmaxf(tile[ly+1][x+1], tile[ly+2][x+1])));
        if (raw < m) {
            if (m - raw >= MARGIN_ && raw < 8.0f) continue;   // safe raw-space reject
            if (sigf(m) > sigf(raw)) continue;                // exact sigmoid-space tie check
        }
        float s = sigf(raw);                                  // exact reference sigmoid
        if (!(s >= THRESH_)) continue;
        int ind = (y0 + ly)*W_ + x;
        unsigned lo = 0xFFFFFFFFu - (unsigned)(c*HW_ + ind);
        unsigned long long key = ((unsigned long long)__float_as_uint(s) << 32) | lo;
        int bin = (int)(unsigned)(key >> 48) - 0x3E4C;
        bin = max(0, min(319, bin));
        atomicAdd(&g_hist[b][bin], 1);                        // RED, spread over 288 blocks
        int p = atomicAdd(&lcnt, 1);
        if (p < LBUF_) lbuf[p] = key;
        else {
            int gp = atomicAdd(&g_cnt[b], 1);
            if (gp < CAP_) g_cand[b][gp] = key;
        }
    }
    __syncthreads();
    int n = min(lcnt, LBUF_);
    if (x == 0) gbase = atomicAdd(&g_cnt[b], n);
    __syncthreads();
    int gb = gbase;
    for (int i = x; i < n; i += W_) {
        int gp = gb + i;
        if (gp < CAP_) g_cand[b][gp] = lbuf[i];
    }
}

// ---------------- fused top-100 select + final math, one block per batch ----------------
__constant__ int c_chan[24] = {0,1,2,3,4,5,6,7,8,
                               26,28,30,32,34,36,38,40,42,44,
                               45,46,47,48,49};

__global__ void __launch_bounds__(NT_) k_selfin(
        const float* __restrict__ pred_reg,
        const float* __restrict__ calib,
        const float* __restrict__ pad_size,
        const float* __restrict__ dim_mean,
        float* __restrict__ out) {
    const int b    = blockIdx.x;
    const int tid  = threadIdx.x;            // 0..511
    const int lane = tid & 31, w = tid >> 5;
    __shared__ int S[NT_];                   // bin suffix sums
    __shared__ int wtot[16];
    __shared__ int SS[256];
    __shared__ unsigned long long surv[SURV_];
    __shared__ float gv[K_][24];
    __shared__ int s_bstar, s_b2, s_scount;

    // capture state in registers, THEN barrier, THEN reset (no read/write race)
    int n  = g_cnt[b];
    int hv = g_hist[b][tid];
    __syncthreads();
    if (tid == 0) g_cnt[b] = 0;
    g_hist[b][tid] = 0;

    if (n > CAP_) n = CAP_;
    int target = n < K_ ? n : K_;

    if (n > 0) {
        // warp-shuffle suffix scan over 512 bins (2 block syncs total)
        int val = hv;
        #pragma unroll
        for (int off = 1; off < 32; off <<= 1) {
            int tv = __shfl_down_sync(0xFFFFFFFFu, val, off);
            if (lane + off < 32) val += tv;
        }
        if (lane == 0) wtot[w] = val;        // warp total
        __syncthreads();
        if (w == 0) {
            int tv = (lane < 16) ? wtot[lane] : 0;
            #pragma unroll
            for (int off = 1; off < 16; off <<= 1) {
                int t2 = __shfl_down_sync(0xFFFFFFFFu, tv, off);
                if (lane + off < 16) tv += t2;
            }
            if (lane < 16) wtot[lane] = tv;  // suffix over warp totals
        }
        __syncthreads();
        int suffix = val + ((w + 1 < 16) ? wtot[w + 1] : 0);
        S[tid] = suffix;
        if (tid == 0) s_scount = 0;
        __syncthreads();
        {
            int nxt = (tid < NT_-1) ? S[tid + 1] : 0;
            if (S[tid] >= target && nxt < target) s_bstar = tid;
        }
        __syncthreads();
        const int bstar = s_bstar;
        const int inBinPlusAbove = S[bstar];

        if (inBinPlusAbove <= SURV_) {
            // common path: take whole cutoff bin, bitonic restores exact order
            for (int i = tid; i < n; i += NT_) {
                unsigned long long key = g_cand[b][i];
                int bin = (int)(unsigned)(key >> 48) - 0x3E4C;
                bin = max(0, min(319, bin));
                if (bin >= bstar) {
                    int p = atomicAdd(&s_scount, 1);
                    if (p < SURV_) surv[p] = key;
                }
            }
        } else {
            // rare fat-bin path: 8-bit refinement
            const int m = max(1, target - ((bstar + 1 < NT_) ? S[bstar + 1] : 0));
            if (tid < 256) SS[tid] = 0;
            __syncthreads();
            for (int i = tid; i < n; i += NT_) {
                unsigned long long key = g_cand[b][i];
                int bin = (int)(unsigned)(key >> 48) - 0x3E4C;
                bin = max(0, min(319, bin));
                if (bin == bstar) atomicAdd(&SS[(unsigned)(key >> 40) & 0xFF], 1);
            }
            __syncthreads();
            if (tid == 0) {
                int acc = 0, b2 = 0;
                for (int s = 255; s >= 0; --s) { acc += SS[s]; if (acc >= m) { b2 = s; break; } }
                s_b2 = b2;
            }
            __syncthreads();
            const int b2 = s_b2;
            for (int i = tid; i < n; i += NT_) {
                unsigned long long key = g_cand[b][i];
                int bin = (int)(unsigned)(key >> 48) - 0x3E4C;
                bin = max(0, min(319, bin));
                bool take = (bin > bstar) || (bin == bstar && (int)((key >> 40) & 0xFF) >= b2);
                if (take) {
                    int p = atomicAdd(&s_scount, 1);
                    if (p < SURV_) surv[p] = key;
                }
            }
        }
        __syncthreads();
        int sc = min(s_scount, SURV_);
        int P = 128; while (P < sc) P <<= 1;
        for (int i = tid; i < P; i += NT_) if (i >= sc) surv[i] = 0ULL;
        __syncthreads();

        // bitonic sort descending on full 64-bit keys (exact reference tie order)
        for (int k = 2; k <= P; k <<= 1) {
            for (int j = k >> 1; j > 0; j >>= 1) {
                for (int i = tid; i < P; i += NT_) {
                    int ixj = i ^ j;
                    if (ixj > i) {
                        bool dir = ((i & k) == 0);
                        unsigned long long a = surv[i], cbb = surv[ixj];
                        if ((a < cbb) == dir) { surv[i] = cbb; surv[ixj] = a; }
                    }
                }
                __syncthreads();
            }
        }

        // gather 24 channels per selected detection (latency-parallel)
        const float* rbase = pred_reg + (size_t)b * CREG_ * HW_;
        for (int i = tid; i < target * 24; i += NT_) {
            int d  = i / 24;
            int ch = i % 24;
            unsigned lo = 0xFFFFFFFFu - (unsigned)(surv[d] & 0xFFFFFFFFu);
            int ind = (int)(lo % HW_);
            gv[d][ch] = __ldg(&rbase[c_chan[ch] * HW_ + ind]);
        }
        __syncthreads();
    }

    if (tid >= K_) return;
    float* row = out + (size_t)(b*K_ + tid) * NOUT_;
    if (tid >= target) {
        #pragma unroll
        for (int j = 0; j < NOUT_; ++j) row[j] = 0.0f;
        return;
    }

    unsigned long long key = surv[tid];
    float score = __uint_as_float((unsigned)(key >> 32));
    unsigned lo = 0xFFFFFFFFu - (unsigned)(key & 0xFFFFFFFFu);
    int cls = (int)(lo / HW_);
    int ind = (int)(lo % HW_);
    float fx = (float)(ind % W_);
    float fy = (float)(ind / W_);
    const float* v = gv[tid];

    float fu = calib[b*4+0], cu = calib[b*4+1], fv = calib[b*4+2], cv = calib[b*4+3];
    float pw = pad_size[b*2+0], ph = pad_size[b*2+1];

    float r0 = fmaxf(v[0], 0.f), r1 = fmaxf(v[1], 0.f);
    float r2 = fmaxf(v[2], 0.f), r3 = fmaxf(v[3], 0.f);
    const float HIX = (float)(W_*4 - 1), HIY = (float)(H_*4 - 1);
    float bx0 = fminf(fmaxf((fx - r0)*4.f - pw, 0.f), HIX);
    float by0 = fminf(fmaxf((fy - r1)*4.f - ph, 0.f), HIY);
    float bx1 = fminf(fmaxf((fx + r2)*4.f - pw, 0.f), HIX);
    float by1 = fminf(fmaxf((fy + r3)*4.f - ph, 0.f), HIY);

    const float* dm = dim_mean + cls*3;
    float d0 = expf(v[6]) * dm[0];
    float d1 = expf(v[7]) * dm[1];
    float d2 = expf(v[8]) * dm[2];
    float h3d = d1;

    float fh = fu * h3d;
    float d_ctr = fh / (fmaxf(v[17] - v[18], 0.f)*4.f + EPS_);
    float d_02  = 0.5f * (fh / (fmaxf(v[9]  - v[13], 0.f)*4.f + EPS_)
                        + fh / (fmaxf(v[11] - v[15], 0.f)*4.f + EPS_));
    float d_13  = 0.5f * (fh / (fmaxf(v[10] - v[14], 0.f)*4.f + EPS_)
                        + fh / (fmaxf(v[12] - v[16], 0.f)*4.f + EPS_));
    float kd0 = fminf(fmaxf(d_ctr, 0.1f), 100.f);
    float kd1 = fminf(fmaxf(d_02 , 0.1f), 100.f);
    float kd2 = fminf(fmaxf(d_13 , 0.1f), 100.f);

    float doff   = v[22];
    float sgd    = 1.0f / (1.0f + expf(-doff));
    float direct = fminf(fmaxf(1.0f / sgd - 1.0f, 0.1f), 100.f);

    float u0 = expf(v[23]);
    float u1 = expf(v[19]);
    float u2 = expf(v[20]);
    float u3 = expf(v[21]);
    float w0 = 1.f/u0, w1 = 1.f/u1, w2 = 1.f/u2, w3 = 1.f/u3;
    float Sw = w0 + w1 + w2 + w3;
    w0 /= Sw; w1 /= Sw; w2 /= Sw; w3 /= Sw;
    float depth = direct*w0 + kd0*w1 + kd1*w2 + kd2*w3;
    float derr  = w0*u0 + w1*u1 + w2*u2 + w3*u3;

    float projx = (fx + v[4])*4.f - pw;
    float projy = (fy + v[5])*4.f - ph;
    float x3 = (projx - cu) * depth / fu;
    float y3 = (projy - cv) * depth / fv;

    row[0]  = (float)cls;
    row[1]  = score;
    row[2]  = bx0;  row[3]  = by0;  row[4]  = bx1;  row[5]  = by1;
    row[6]  = d0;   row[7]  = d1;   row[8]  = d2;
    row[9]  = x3;   row[10] = y3;   row[11] = depth;
    row[12] = derr;
}

extern "C" void kernel_launch(void* const* d_in, const int* in_sizes, int n_in,
                              void* d_out, int out_size) {
    const float* pred_hmp = (const float*)d_in[0];
    const float* pred_reg = (const float*)d_in[1];
    const float* calib    = (const float*)d_in[2];
    const float* pad_size = (const float*)d_in[3];
    const float* dim_mean = (const float*)d_in[4];
    float* out = (float*)d_out;

    k_nms<<<B_*NCLS_*NTB, W_>>>(pred_hmp);
    k_selfin<<<B_, NT_>>>(pred_reg, calib, pad_size, dim_mean, out);
}